// round 8
// baseline (speedup 1.0000x reference)
#include <cuda_runtime.h>
#include <cuda_bf16.h>
#include <cstdint>
#include <math.h>

#define NB 16384          // batch
#define NC 2              // contrast views
#define ND 1024           // feature dim
#define NSUB 16
#define NLAB 8
#define KG 128            // NSUB*NLAB groups
#define NROWS 32768       // NB*NC
#define BK 32             // k-chunk (elements)
#define NCHUNK (ND / BK)  // 32
#define LDSS 40           // bf16 elems per smem row (80B = 20 banks, conflict-free)

#define ASTG (64 * LDSS)             // A stage size (elems)
#define BSTG (128 * LDSS)            // B stage size (elems)
#define OFF_AH 0                     // [2][64][LDSS]
#define OFF_AL (2 * ASTG)
#define OFF_BH (4 * ASTG)            // [2][128][LDSS]
#define OFF_BL (OFF_BH + 2 * BSTG)
#define SMEM_ELEMS (OFF_BL + 2 * BSTG)
#define DYN_SMEM (SMEM_ELEMS * 2)    // bytes = 61440

// ---------------- scratch (device globals; no runtime allocation) ----------------
__device__ __align__(16) __nv_bfloat16 g_cent_h[KG * ND];
__device__ __align__(16) __nv_bfloat16 g_cent_l[KG * ND];
__device__ float g_counts[KG];
__device__ int   g_hist[KG];
__device__ int   g_gid[NB];
__device__ int   g_offsets[KG + 1];
__device__ int   g_cursor[KG];
__device__ int   g_rowlist[NB];
__device__ float g_cnorm[KG];
__device__ float g_S[(size_t)NROWS * KG];  // 16 MB
__device__ float g_rownorm[NROWS];
__device__ float g_sqsum[KG];
__device__ float g_invdens[KG];

// ---------------- helpers ----------------
__device__ __forceinline__ uint32_t pack_bf16(float lo, float hi) {
    uint32_t r;
    asm("cvt.rn.bf16x2.f32 %0, %1, %2;" : "=r"(r) : "f"(hi), "f"(lo));
    return r;
}
__device__ __forceinline__ float bf_lo(uint32_t v) {
    return __bfloat162float(__ushort_as_bfloat16((unsigned short)(v & 0xFFFFu)));
}
__device__ __forceinline__ float bf_hi(uint32_t v) {
    return __bfloat162float(__ushort_as_bfloat16((unsigned short)(v >> 16)));
}
__device__ __forceinline__ void hmma_bf16(float* d, const uint32_t* a, const uint32_t* b) {
    asm volatile(
        "mma.sync.aligned.m16n8k16.row.col.f32.bf16.bf16.f32 "
        "{%0,%1,%2,%3}, {%4,%5,%6,%7}, {%8,%9}, {%0,%1,%2,%3};"
        : "+f"(d[0]), "+f"(d[1]), "+f"(d[2]), "+f"(d[3])
        : "r"(a[0]), "r"(a[1]), "r"(a[2]), "r"(a[3]), "r"(b[0]), "r"(b[1]));
}
__device__ __forceinline__ void ldm_x4(uint32_t* r, uint32_t addr) {
    asm volatile("ldmatrix.sync.aligned.m8n8.x4.shared.b16 {%0,%1,%2,%3}, [%4];"
                 : "=r"(r[0]), "=r"(r[1]), "=r"(r[2]), "=r"(r[3]) : "r"(addr));
}

// ---------------- K0a: zero accumulators ----------------
__global__ void zero_kernel(float* __restrict__ out) {
    int t = threadIdx.x;  // 128
    g_hist[t] = 0;
    g_sqsum[t] = 0.0f;
    g_cnorm[t] = 0.0f;
    if (t == 0) out[0] = 0.0f;
}

// ---------------- K0b: gid + histogram ----------------
__global__ void hist_kernel(const int* __restrict__ subject,
                            const int* __restrict__ labels) {
    __shared__ int hist[KG];
    int t = threadIdx.x;
    if (t < KG) hist[t] = 0;
    __syncthreads();
    int b = blockIdx.x * 256 + t;
    int g = subject[b] * NLAB + labels[b];
    g_gid[b] = g;
    atomicAdd(&hist[g], 1);
    __syncthreads();
    if (t < KG && hist[t]) atomicAdd(&g_hist[t], hist[t]);
}

// ---------------- K0c: offsets / counts ----------------
__global__ void offsets_kernel() {
    int t = threadIdx.x;  // 128
    __shared__ int h[KG];
    h[t] = g_hist[t];
    __syncthreads();
    int acc = 0;
    for (int j = 0; j < t; j++) acc += h[j];
    g_offsets[t] = acc;
    g_cursor[t] = acc;
    g_counts[t] = 2.0f * (float)h[t];
    if (t == KG - 1) g_offsets[KG] = acc + h[t];
}

// ---------------- K0d: two-level scatter (low contention) ----------------
__global__ void scatter_kernel() {
    __shared__ int lhist[KG];
    __shared__ int lbase[KG];
    int t = threadIdx.x;  // 256
    if (t < KG) lhist[t] = 0;
    __syncthreads();
    int b = blockIdx.x * 256 + t;
    int g = g_gid[b];
    int lrank = atomicAdd(&lhist[g], 1);
    __syncthreads();
    if (t < KG) lbase[t] = lhist[t] ? atomicAdd(&g_cursor[t], lhist[t]) : 0;
    __syncthreads();
    g_rowlist[lbase[g] + lrank] = b;
}

// ---------------- K1: centroids (fp32) -> bf16 hi/lo + cnorm ----------------
__global__ __launch_bounds__(256) void centroid_kernel(const float* __restrict__ X) {
    int g = blockIdx.y;
    int d = blockIdx.x * 256 + threadIdx.x;
    int beg = g_offsets[g], end = g_offsets[g + 1];
    float acc = 0.0f;
    int j = beg;
    for (; j + 4 <= end; j += 4) {
        int b0 = g_rowlist[j + 0], b1 = g_rowlist[j + 1];
        int b2 = g_rowlist[j + 2], b3 = g_rowlist[j + 3];
        const float* p0 = X + (size_t)b0 * (NC * ND) + d;
        const float* p1 = X + (size_t)b1 * (NC * ND) + d;
        const float* p2 = X + (size_t)b2 * (NC * ND) + d;
        const float* p3 = X + (size_t)b3 * (NC * ND) + d;
        acc += __ldg(p0) + __ldg(p0 + ND);
        acc += __ldg(p1) + __ldg(p1 + ND);
        acc += __ldg(p2) + __ldg(p2 + ND);
        acc += __ldg(p3) + __ldg(p3 + ND);
    }
    for (; j < end; j++) {
        int b = g_rowlist[j];
        const float* p = X + (size_t)b * (NC * ND) + d;
        acc += __ldg(p) + __ldg(p + ND);
    }
    float cnt = g_counts[g];
    float cv = (cnt > 0.0f) ? (acc / cnt) : 0.0f;

    __nv_bfloat16 ch = __float2bfloat16(cv);
    float chf = __bfloat162float(ch);
    __nv_bfloat16 cl = __float2bfloat16(cv - chf);
    g_cent_h[g * ND + d] = ch;
    g_cent_l[g * ND + d] = cl;

    float sq = cv * cv;
    #pragma unroll
    for (int off = 16; off; off >>= 1) sq += __shfl_down_sync(0xFFFFFFFFu, sq, off);
    __shared__ float wsum[8];
    if ((threadIdx.x & 31) == 0) wsum[threadIdx.x >> 5] = sq;
    __syncthreads();
    if (threadIdx.x == 0) {
        float s = 0.0f;
        #pragma unroll
        for (int w = 0; w < 8; w++) s += wsum[w];
        atomicAdd(&g_cnorm[g], s);
    }
}

// ---------------- K2: split-bf16 HMMA GEMM, double-buffered, ldmatrix ----------------
// CTA 64x128, 4 warps (2x2), warp tile 32x64, BK=32, 2-stage smem pipeline.
__global__ __launch_bounds__(128, 3) void gemm_kernel(const float* __restrict__ X) {
    extern __shared__ __nv_bfloat16 sm[];

    const int t = threadIdx.x;
    const int wid = t >> 5;
    const int lane = t & 31;
    const int lr = lane >> 2;        // 0..7
    const int lc = (lane & 3) * 2;   // 0,2,4,6
    const int warp_m = (wid & 1) * 32;
    const int warp_n = (wid >> 1) * 64;

    const int block_m = blockIdx.x * 64;
    const int c = block_m >> 14;           // view index
    const int b0 = block_m & (NB - 1);
    const float* Abase = X + (size_t)b0 * (NC * ND) + (size_t)c * ND;

    // fill mappings
    const int ar = t >> 3;       // 0..15
    const int ak = (t & 7) * 4;  // 0..28
    const int br = t >> 2;       // 0..31
    const int bk = (t & 3) * 8;  // 0,8,16,24

    // ldmatrix per-lane source coords
    const int a_r = lane & 15;               // row within m16
    const int a_c = (lane >> 4) * 8;         // 0 or 8 (k offset)
    const int b_r = (lane & 7) + ((lane >> 4) << 3);  // n offset within n16
    const int b_c = ((lane >> 3) & 1) * 8;   // 0 or 8 (k offset)

    const uint32_t sbase = (uint32_t)__cvta_generic_to_shared(sm);

    float acc[2][8][4];
    #pragma unroll
    for (int mi = 0; mi < 2; mi++)
        #pragma unroll
        for (int ni = 0; ni < 8; ni++)
            #pragma unroll
            for (int j = 0; j < 4; j++) acc[mi][ni][j] = 0.0f;
    float rn[4] = {0, 0, 0, 0};

    float4 pav[4];
    uint4 pbh[4], pbl[4];

    // ---- prefetch chunk 0 ----
    #pragma unroll
    for (int p = 0; p < 4; p++)
        pav[p] = *(const float4*)(Abase + (size_t)(p * 16 + ar) * (NC * ND) + ak);
    #pragma unroll
    for (int p = 0; p < 4; p++) {
        pbh[p] = *(const uint4*)&g_cent_h[(p * 32 + br) * ND + bk];
        pbl[p] = *(const uint4*)&g_cent_l[(p * 32 + br) * ND + bk];
    }

    // ---- store chunk 0 into stage 0 ----
    #pragma unroll
    for (int p = 0; p < 4; p++) {
        float4 v = pav[p];
        rn[p] += v.x * v.x + v.y * v.y + v.z * v.z + v.w * v.w;
        uint32_t h0 = pack_bf16(v.x, v.y);
        uint32_t h1 = pack_bf16(v.z, v.w);
        uint32_t l0 = pack_bf16(v.x - bf_lo(h0), v.y - bf_hi(h0));
        uint32_t l1 = pack_bf16(v.z - bf_lo(h1), v.w - bf_hi(h1));
        int r = p * 16 + ar;
        *(uint2*)&sm[OFF_AH + r * LDSS + ak] = make_uint2(h0, h1);
        *(uint2*)&sm[OFF_AL + r * LDSS + ak] = make_uint2(l0, l1);
    }
    #pragma unroll
    for (int p = 0; p < 4; p++) {
        int g = p * 32 + br;
        *(uint4*)&sm[OFF_BH + g * LDSS + bk] = pbh[p];
        *(uint4*)&sm[OFF_BL + g * LDSS + bk] = pbl[p];
    }
    __syncthreads();

    for (int chk = 0; chk < NCHUNK; chk++) {
        const int cur = chk & 1;
        const int nxt = cur ^ 1;
        const bool has_next = (chk + 1 < NCHUNK);

        // ---- issue global loads for next chunk (overlap with MMA) ----
        if (has_next) {
            const int k0 = (chk + 1) * BK;
            #pragma unroll
            for (int p = 0; p < 4; p++)
                pav[p] = *(const float4*)(Abase + (size_t)(p * 16 + ar) * (NC * ND) + k0 + ak);
            #pragma unroll
            for (int p = 0; p < 4; p++) {
                pbh[p] = *(const uint4*)&g_cent_h[(p * 32 + br) * ND + k0 + bk];
                pbl[p] = *(const uint4*)&g_cent_l[(p * 32 + br) * ND + k0 + bk];
            }
        }

        // ---- MMA over current stage (ldmatrix fragment loads) ----
        const uint32_t aBaseH = sbase + 2 * (OFF_AH + cur * ASTG);
        const uint32_t aBaseL = sbase + 2 * (OFF_AL + cur * ASTG);
        const uint32_t bBaseH = sbase + 2 * (OFF_BH + cur * BSTG);
        const uint32_t bBaseL = sbase + 2 * (OFF_BL + cur * BSTG);
        #pragma unroll
        for (int kk = 0; kk < BK; kk += 16) {
            uint32_t ah[2][4], al[2][4];
            #pragma unroll
            for (int mi = 0; mi < 2; mi++) {
                uint32_t off = 2 * ((warp_m + mi * 16 + a_r) * LDSS + kk + a_c);
                ldm_x4(ah[mi], aBaseH + off);
                ldm_x4(al[mi], aBaseL + off);
            }
            #pragma unroll
            for (int p = 0; p < 4; p++) {   // ni pairs
                uint32_t bh[4], bl[4];
                uint32_t off = 2 * ((warp_n + p * 16 + b_r) * LDSS + kk + b_c);
                ldm_x4(bh, bBaseH + off);
                ldm_x4(bl, bBaseL + off);
                #pragma unroll
                for (int mi = 0; mi < 2; mi++) {
                    hmma_bf16(acc[mi][2 * p], ah[mi], bh);
                    hmma_bf16(acc[mi][2 * p], ah[mi], bl);
                    hmma_bf16(acc[mi][2 * p], al[mi], bh);
                    hmma_bf16(acc[mi][2 * p + 1], ah[mi], bh + 2);
                    hmma_bf16(acc[mi][2 * p + 1], ah[mi], bl + 2);
                    hmma_bf16(acc[mi][2 * p + 1], al[mi], bh + 2);
                }
            }
        }

        // ---- convert & store next chunk into other stage ----
        if (has_next) {
            #pragma unroll
            for (int p = 0; p < 4; p++) {
                float4 v = pav[p];
                rn[p] += v.x * v.x + v.y * v.y + v.z * v.z + v.w * v.w;
                uint32_t h0 = pack_bf16(v.x, v.y);
                uint32_t h1 = pack_bf16(v.z, v.w);
                uint32_t l0 = pack_bf16(v.x - bf_lo(h0), v.y - bf_hi(h0));
                uint32_t l1 = pack_bf16(v.z - bf_lo(h1), v.w - bf_hi(h1));
                int r = p * 16 + ar;
                *(uint2*)&sm[OFF_AH + nxt * ASTG + r * LDSS + ak] = make_uint2(h0, h1);
                *(uint2*)&sm[OFF_AL + nxt * ASTG + r * LDSS + ak] = make_uint2(l0, l1);
            }
            #pragma unroll
            for (int p = 0; p < 4; p++) {
                int g = p * 32 + br;
                *(uint4*)&sm[OFF_BH + nxt * BSTG + g * LDSS + bk] = pbh[p];
                *(uint4*)&sm[OFF_BL + nxt * BSTG + g * LDSS + bk] = pbl[p];
            }
        }
        __syncthreads();
    }

    // ---- rownorm: reduce over 8 lanes sharing each row ----
    #pragma unroll
    for (int p = 0; p < 4; p++) {
        float v = rn[p];
        v += __shfl_xor_sync(0xFFFFFFFFu, v, 1);
        v += __shfl_xor_sync(0xFFFFFFFFu, v, 2);
        v += __shfl_xor_sync(0xFFFFFFFFu, v, 4);
        if ((t & 7) == 0) g_rownorm[block_m + p * 16 + ar] = v;
    }

    // ---- epilogue: write S ----
    #pragma unroll
    for (int mi = 0; mi < 2; mi++) {
        #pragma unroll
        for (int ni = 0; ni < 8; ni++) {
            int row = block_m + warp_m + mi * 16 + lr;
            int col = warp_n + ni * 8 + lc;
            *(float2*)&g_S[(size_t)row * KG + col] =
                make_float2(acc[mi][ni][0], acc[mi][ni][1]);
            *(float2*)&g_S[(size_t)(row + 8) * KG + col] =
                make_float2(acc[mi][ni][2], acc[mi][ni][3]);
        }
    }
}

// ---------------- K3: per-row dist -> per-group sum of sqrt(dist) ----------------
__global__ void dist_kernel() {
    __shared__ float bins[KG];
    int t = threadIdx.x;
    if (t < KG) bins[t] = 0.0f;
    __syncthreads();
    int i = blockIdx.x * 256 + t;
    int b = i & (NB - 1);
    int g = g_gid[b];
    float s = g_S[(size_t)i * KG + g];
    float d2 = g_rownorm[i] - 2.0f * s + g_cnorm[g];
    float dist = sqrtf(fmaxf(d2, 0.0f));
    atomicAdd(&bins[g], sqrtf(dist));
    __syncthreads();
    if (t < KG) atomicAdd(&g_sqsum[t], bins[t]);
}

// ---------------- K4: density ----------------
__global__ void density_kernel() {
    int t = threadIdx.x;  // 128
    __shared__ float dens[KG];
    __shared__ float red[KG];
    __shared__ float sorted[KG];

    float cnt = g_counts[t];
    float d = (g_sqsum[t] / cnt) / logf(cnt + 10.0f);
    bool invalid = (cnt <= 1.0f);
    red[t] = invalid ? -3.4e38f : d;
    __syncthreads();
    for (int off = 64; off; off >>= 1) {
        if (t < off) red[t] = fmaxf(red[t], red[t + off]);
        __syncthreads();
    }
    float dmax = red[0];
    __syncthreads();
    if (invalid) d = dmax;
    dens[t] = d;
    __syncthreads();

    int rank = 0;
    float v = d;
    for (int j = 0; j < KG; j++) {
        float w = dens[j];
        rank += (int)((w < v) || ((w == v) && (j < t)));
    }
    sorted[rank] = v;
    __syncthreads();

    float qlo = sorted[12] + 0.7f * (sorted[13] - sorted[12]);
    float qhi = sorted[114] + 0.3f * (sorted[115] - sorted[114]);
    float dc = fminf(fmaxf(d, qlo), qhi);
    red[t] = dc;
    __syncthreads();
    for (int off = 64; off; off >>= 1) {
        if (t < off) red[t] += red[t + off];
        __syncthreads();
    }
    float mean = red[0] * (1.0f / 128.0f);
    float fin = 0.1f * dc / mean;
    g_invdens[t] = 1.0f / fin;
}

// ---------------- K5: masked log-softmax loss ----------------
__global__ __launch_bounds__(256) void loss_kernel(const int* __restrict__ subject,
                                                   const int* __restrict__ labels,
                                                   float* __restrict__ out) {
    int warp_in_block = threadIdx.x >> 5;
    int lane = threadIdx.x & 31;
    int i = blockIdx.x * 8 + warp_in_block;
    int b = i & (NB - 1);

    float4 sv = *(const float4*)&g_S[(size_t)i * KG + lane * 4];
    float4 idv = *(const float4*)&g_invdens[lane * 4];
    float s0 = sv.x * idv.x, s1 = sv.y * idv.y, s2 = sv.z * idv.z, s3 = sv.w * idv.w;

    float mx = fmaxf(fmaxf(s0, s1), fmaxf(s2, s3));
    #pragma unroll
    for (int off = 16; off; off >>= 1) mx = fmaxf(mx, __shfl_xor_sync(0xFFFFFFFFu, mx, off));

    int sub = subject[b];
    int lab = labels[b];

    float sim[4] = {s0, s1, s2, s3};
    float sumexp = 0.0f, possum = 0.0f;
    #pragma unroll
    for (int j = 0; j < 4; j++) {
        int g = lane * 4 + j;
        bool m = ((g & 7) == lab) && ((g >> 3) != sub);
        float p = m ? (sim[j] - mx) : 0.0f;
        sumexp += expf(p);
        possum += p;
    }
    #pragma unroll
    for (int off = 16; off; off >>= 1) {
        sumexp += __shfl_xor_sync(0xFFFFFFFFu, sumexp, off);
        possum += __shfl_xor_sync(0xFFFFFFFFu, possum, off);
    }

    __shared__ float wloss[8];
    if (lane == 0)
        wloss[warp_in_block] = logf(sumexp) - possum * (1.0f / 15.0f);
    __syncthreads();
    if (threadIdx.x == 0) {
        float s = 0.0f;
        #pragma unroll
        for (int w = 0; w < 8; w++) s += wloss[w];
        atomicAdd(out, s * (1.0f / (float)NROWS));
    }
}

// ---------------- launch ----------------
extern "C" void kernel_launch(void* const* d_in, const int* in_sizes, int n_in,
                              void* d_out, int out_size) {
    const float* X       = (const float*)d_in[0];
    const int*   subject = (const int*)d_in[1];
    const int*   labels  = (const int*)d_in[2];
    float* out = (float*)d_out;

    static bool attr_set = false;
    if (!attr_set) {
        cudaFuncSetAttribute(gemm_kernel,
                             cudaFuncAttributeMaxDynamicSharedMemorySize, DYN_SMEM);
        attr_set = true;
    }

    zero_kernel<<<1, 128>>>(out);
    hist_kernel<<<NB / 256, 256>>>(subject, labels);
    offsets_kernel<<<1, 128>>>();
    scatter_kernel<<<64, 256>>>();
    dim3 cgrid(ND / 256, KG);
    centroid_kernel<<<cgrid, 256>>>(X);
    gemm_kernel<<<NROWS / 64, 128, DYN_SMEM>>>(X);
    dist_kernel<<<NROWS / 256, 256>>>();
    density_kernel<<<1, 128>>>();
    loss_kernel<<<NROWS / 8, 256>>>(subject, labels, out);
}

// round 9
// speedup vs baseline: 1.3919x; 1.3919x over previous
#include <cuda_runtime.h>
#include <cuda_bf16.h>
#include <cstdint>
#include <math.h>

#define NB 16384          // batch
#define NC 2              // contrast views
#define ND 1024           // feature dim
#define NSUB 16
#define NLAB 8
#define KG 128            // NSUB*NLAB groups
#define NROWS 32768       // NB*NC
#define BK 32             // k-chunk (elements)
#define NCHUNK (ND / BK)  // 32
#define LDSS 40           // bf16 elems per smem row (80B = 20 banks, conflict-free)

#define ASTG (64 * LDSS)             // A stage size (elems)
#define BSTG (128 * LDSS)            // B stage size (elems)
#define OFF_AH 0                     // [2][64][LDSS]
#define OFF_AL (2 * ASTG)
#define OFF_BH (4 * ASTG)            // [2][128][LDSS]
#define OFF_BL (OFF_BH + 2 * BSTG)
#define SMEM_ELEMS (OFF_BL + 2 * BSTG)
#define DYN_SMEM (SMEM_ELEMS * 2)    // bytes = 61440

// ---------------- scratch (device globals; no runtime allocation) ----------------
__device__ __align__(16) __nv_bfloat16 g_cent_h[KG * ND];
__device__ __align__(16) __nv_bfloat16 g_cent_l[KG * ND];
__device__ float g_counts[KG];
__device__ int   g_hist[KG];
__device__ int   g_gid[NB];
__device__ int   g_offsets[KG + 1];
__device__ int   g_cursor[KG];
__device__ int   g_rowlist[NB];
__device__ float g_cnorm[KG];
__device__ float g_S[(size_t)NROWS * KG];  // 16 MB
__device__ float g_rownorm[NROWS];
__device__ float g_sqsum[KG];
__device__ float g_invdens[KG];

// ---------------- helpers ----------------
__device__ __forceinline__ uint32_t pack_bf16(float lo, float hi) {
    uint32_t r;
    asm("cvt.rn.bf16x2.f32 %0, %1, %2;" : "=r"(r) : "f"(hi), "f"(lo));
    return r;
}
__device__ __forceinline__ float bf_lo(uint32_t v) {
    return __bfloat162float(__ushort_as_bfloat16((unsigned short)(v & 0xFFFFu)));
}
__device__ __forceinline__ float bf_hi(uint32_t v) {
    return __bfloat162float(__ushort_as_bfloat16((unsigned short)(v >> 16)));
}
__device__ __forceinline__ void hmma_bf16(float* d, const uint32_t* a, const uint32_t* b) {
    asm volatile(
        "mma.sync.aligned.m16n8k16.row.col.f32.bf16.bf16.f32 "
        "{%0,%1,%2,%3}, {%4,%5,%6,%7}, {%8,%9}, {%0,%1,%2,%3};"
        : "+f"(d[0]), "+f"(d[1]), "+f"(d[2]), "+f"(d[3])
        : "r"(a[0]), "r"(a[1]), "r"(a[2]), "r"(a[3]), "r"(b[0]), "r"(b[1]));
}
__device__ __forceinline__ void ldm_x4(uint32_t* r, uint32_t addr) {
    asm volatile("ldmatrix.sync.aligned.m8n8.x4.shared.b16 {%0,%1,%2,%3}, [%4];"
                 : "=r"(r[0]), "=r"(r[1]), "=r"(r[2]), "=r"(r[3]) : "r"(addr));
}

// ---------------- K0a: zero accumulators ----------------
__global__ void zero_kernel(float* __restrict__ out) {
    int t = threadIdx.x;  // 128
    g_hist[t] = 0;
    g_sqsum[t] = 0.0f;
    g_cnorm[t] = 0.0f;
    if (t == 0) out[0] = 0.0f;
}

// ---------------- K0b: gid + histogram ----------------
__global__ void hist_kernel(const int* __restrict__ subject,
                            const int* __restrict__ labels) {
    __shared__ int hist[KG];
    int t = threadIdx.x;
    if (t < KG) hist[t] = 0;
    __syncthreads();
    int b = blockIdx.x * 256 + t;
    int g = subject[b] * NLAB + labels[b];
    g_gid[b] = g;
    atomicAdd(&hist[g], 1);
    __syncthreads();
    if (t < KG && hist[t]) atomicAdd(&g_hist[t], hist[t]);
}

// ---------------- K0c: offsets / counts ----------------
__global__ void offsets_kernel() {
    int t = threadIdx.x;  // 128
    __shared__ int h[KG];
    h[t] = g_hist[t];
    __syncthreads();
    int acc = 0;
    for (int j = 0; j < t; j++) acc += h[j];
    g_offsets[t] = acc;
    g_cursor[t] = acc;
    g_counts[t] = 2.0f * (float)h[t];
    if (t == KG - 1) g_offsets[KG] = acc + h[t];
}

// ---------------- K0d: two-level scatter (low contention) ----------------
__global__ void scatter_kernel() {
    __shared__ int lhist[KG];
    __shared__ int lbase[KG];
    int t = threadIdx.x;  // 256
    if (t < KG) lhist[t] = 0;
    __syncthreads();
    int b = blockIdx.x * 256 + t;
    int g = g_gid[b];
    int lrank = atomicAdd(&lhist[g], 1);
    __syncthreads();
    if (t < KG) lbase[t] = lhist[t] ? atomicAdd(&g_cursor[t], lhist[t]) : 0;
    __syncthreads();
    g_rowlist[lbase[g] + lrank] = b;
}

// ---------------- K1: centroids (fp32) -> bf16 hi/lo + cnorm ----------------
__global__ __launch_bounds__(256) void centroid_kernel(const float* __restrict__ X) {
    int g = blockIdx.y;
    int d = blockIdx.x * 256 + threadIdx.x;
    int beg = g_offsets[g], end = g_offsets[g + 1];
    float acc = 0.0f;
    int j = beg;
    for (; j + 4 <= end; j += 4) {
        int b0 = g_rowlist[j + 0], b1 = g_rowlist[j + 1];
        int b2 = g_rowlist[j + 2], b3 = g_rowlist[j + 3];
        const float* p0 = X + (size_t)b0 * (NC * ND) + d;
        const float* p1 = X + (size_t)b1 * (NC * ND) + d;
        const float* p2 = X + (size_t)b2 * (NC * ND) + d;
        const float* p3 = X + (size_t)b3 * (NC * ND) + d;
        acc += __ldg(p0) + __ldg(p0 + ND);
        acc += __ldg(p1) + __ldg(p1 + ND);
        acc += __ldg(p2) + __ldg(p2 + ND);
        acc += __ldg(p3) + __ldg(p3 + ND);
    }
    for (; j < end; j++) {
        int b = g_rowlist[j];
        const float* p = X + (size_t)b * (NC * ND) + d;
        acc += __ldg(p) + __ldg(p + ND);
    }
    float cnt = g_counts[g];
    float cv = (cnt > 0.0f) ? (acc / cnt) : 0.0f;

    __nv_bfloat16 ch = __float2bfloat16(cv);
    float chf = __bfloat162float(ch);
    __nv_bfloat16 cl = __float2bfloat16(cv - chf);
    g_cent_h[g * ND + d] = ch;
    g_cent_l[g * ND + d] = cl;

    float sq = cv * cv;
    #pragma unroll
    for (int off = 16; off; off >>= 1) sq += __shfl_down_sync(0xFFFFFFFFu, sq, off);
    __shared__ float wsum[8];
    if ((threadIdx.x & 31) == 0) wsum[threadIdx.x >> 5] = sq;
    __syncthreads();
    if (threadIdx.x == 0) {
        float s = 0.0f;
        #pragma unroll
        for (int w = 0; w < 8; w++) s += wsum[w];
        atomicAdd(&g_cnorm[g], s);
    }
}

// ---------------- K2: split-bf16 HMMA GEMM, double-buffered, ldmatrix ----------------
// CTA 64x128, 4 warps (2x2), warp tile 32x64, BK=32, 2-stage smem pipeline.
// launch_bounds (128,2): reg cap 256 -> no spills; 2 CTAs/SM via smem.
__global__ __launch_bounds__(128, 2) void gemm_kernel(const float* __restrict__ X) {
    extern __shared__ __nv_bfloat16 sm[];

    const int t = threadIdx.x;
    const int wid = t >> 5;
    const int lane = t & 31;
    const int lr = lane >> 2;        // 0..7
    const int lc = (lane & 3) * 2;   // 0,2,4,6
    const int warp_m = (wid & 1) * 32;
    const int warp_n = (wid >> 1) * 64;

    const int block_m = blockIdx.x * 64;
    const int c = block_m >> 14;           // view index
    const int b0 = block_m & (NB - 1);
    const float* Abase = X + (size_t)b0 * (NC * ND) + (size_t)c * ND;

    // fill mappings
    const int ar = t >> 3;       // 0..15
    const int ak = (t & 7) * 4;  // 0..28
    const int br = t >> 2;       // 0..31
    const int bk = (t & 3) * 8;  // 0,8,16,24

    // ldmatrix per-lane source coords
    const int a_r = lane & 15;               // row within m16
    const int a_c = (lane >> 4) * 8;         // 0 or 8 (k offset)
    const int b_r = (lane & 7) + ((lane >> 4) << 3);  // n offset within n16
    const int b_c = ((lane >> 3) & 1) * 8;   // 0 or 8 (k offset)

    const uint32_t sbase = (uint32_t)__cvta_generic_to_shared(sm);

    float acc[2][8][4];
    #pragma unroll
    for (int mi = 0; mi < 2; mi++)
        #pragma unroll
        for (int ni = 0; ni < 8; ni++)
            #pragma unroll
            for (int j = 0; j < 4; j++) acc[mi][ni][j] = 0.0f;
    float rn[4] = {0, 0, 0, 0};

    float4 pav[4];
    uint4 pbh[4], pbl[4];

    // ---- prefetch chunk 0 ----
    #pragma unroll
    for (int p = 0; p < 4; p++)
        pav[p] = *(const float4*)(Abase + (size_t)(p * 16 + ar) * (NC * ND) + ak);
    #pragma unroll
    for (int p = 0; p < 4; p++) {
        pbh[p] = *(const uint4*)&g_cent_h[(p * 32 + br) * ND + bk];
        pbl[p] = *(const uint4*)&g_cent_l[(p * 32 + br) * ND + bk];
    }

    // ---- store chunk 0 into stage 0 ----
    #pragma unroll
    for (int p = 0; p < 4; p++) {
        float4 v = pav[p];
        rn[p] += v.x * v.x + v.y * v.y + v.z * v.z + v.w * v.w;
        uint32_t h0 = pack_bf16(v.x, v.y);
        uint32_t h1 = pack_bf16(v.z, v.w);
        uint32_t l0 = pack_bf16(v.x - bf_lo(h0), v.y - bf_hi(h0));
        uint32_t l1 = pack_bf16(v.z - bf_lo(h1), v.w - bf_hi(h1));
        int r = p * 16 + ar;
        *(uint2*)&sm[OFF_AH + r * LDSS + ak] = make_uint2(h0, h1);
        *(uint2*)&sm[OFF_AL + r * LDSS + ak] = make_uint2(l0, l1);
    }
    #pragma unroll
    for (int p = 0; p < 4; p++) {
        int g = p * 32 + br;
        *(uint4*)&sm[OFF_BH + g * LDSS + bk] = pbh[p];
        *(uint4*)&sm[OFF_BL + g * LDSS + bk] = pbl[p];
    }
    __syncthreads();

    for (int chk = 0; chk < NCHUNK; chk++) {
        const int cur = chk & 1;
        const int nxt = cur ^ 1;
        const bool has_next = (chk + 1 < NCHUNK);

        // ---- issue global loads for next chunk (overlap with MMA) ----
        if (has_next) {
            const int k0 = (chk + 1) * BK;
            #pragma unroll
            for (int p = 0; p < 4; p++)
                pav[p] = *(const float4*)(Abase + (size_t)(p * 16 + ar) * (NC * ND) + k0 + ak);
            #pragma unroll
            for (int p = 0; p < 4; p++) {
                pbh[p] = *(const uint4*)&g_cent_h[(p * 32 + br) * ND + k0 + bk];
                pbl[p] = *(const uint4*)&g_cent_l[(p * 32 + br) * ND + k0 + bk];
            }
        }

        // ---- MMA over current stage (ldmatrix fragment loads) ----
        const uint32_t aBaseH = sbase + 2 * (OFF_AH + cur * ASTG);
        const uint32_t aBaseL = sbase + 2 * (OFF_AL + cur * ASTG);
        const uint32_t bBaseH = sbase + 2 * (OFF_BH + cur * BSTG);
        const uint32_t bBaseL = sbase + 2 * (OFF_BL + cur * BSTG);
        #pragma unroll
        for (int kk = 0; kk < BK; kk += 16) {
            uint32_t ah[2][4], al[2][4];
            #pragma unroll
            for (int mi = 0; mi < 2; mi++) {
                uint32_t off = 2 * ((warp_m + mi * 16 + a_r) * LDSS + kk + a_c);
                ldm_x4(ah[mi], aBaseH + off);
                ldm_x4(al[mi], aBaseL + off);
            }
            #pragma unroll
            for (int p = 0; p < 4; p++) {   // ni pairs
                uint32_t bh[4], bl[4];
                uint32_t off = 2 * ((warp_n + p * 16 + b_r) * LDSS + kk + b_c);
                ldm_x4(bh, bBaseH + off);
                ldm_x4(bl, bBaseL + off);
                #pragma unroll
                for (int mi = 0; mi < 2; mi++) {
                    hmma_bf16(acc[mi][2 * p], ah[mi], bh);
                    hmma_bf16(acc[mi][2 * p], ah[mi], bl);
                    hmma_bf16(acc[mi][2 * p], al[mi], bh);
                    hmma_bf16(acc[mi][2 * p + 1], ah[mi], bh + 2);
                    hmma_bf16(acc[mi][2 * p + 1], ah[mi], bl + 2);
                    hmma_bf16(acc[mi][2 * p + 1], al[mi], bh + 2);
                }
            }
        }

        // ---- convert & store next chunk into other stage ----
        if (has_next) {
            #pragma unroll
            for (int p = 0; p < 4; p++) {
                float4 v = pav[p];
                rn[p] += v.x * v.x + v.y * v.y + v.z * v.z + v.w * v.w;
                uint32_t h0 = pack_bf16(v.x, v.y);
                uint32_t h1 = pack_bf16(v.z, v.w);
                uint32_t l0 = pack_bf16(v.x - bf_lo(h0), v.y - bf_hi(h0));
                uint32_t l1 = pack_bf16(v.z - bf_lo(h1), v.w - bf_hi(h1));
                int r = p * 16 + ar;
                *(uint2*)&sm[OFF_AH + nxt * ASTG + r * LDSS + ak] = make_uint2(h0, h1);
                *(uint2*)&sm[OFF_AL + nxt * ASTG + r * LDSS + ak] = make_uint2(l0, l1);
            }
            #pragma unroll
            for (int p = 0; p < 4; p++) {
                int g = p * 32 + br;
                *(uint4*)&sm[OFF_BH + nxt * BSTG + g * LDSS + bk] = pbh[p];
                *(uint4*)&sm[OFF_BL + nxt * BSTG + g * LDSS + bk] = pbl[p];
            }
        }
        __syncthreads();
    }

    // ---- rownorm: reduce over 8 lanes sharing each row ----
    #pragma unroll
    for (int p = 0; p < 4; p++) {
        float v = rn[p];
        v += __shfl_xor_sync(0xFFFFFFFFu, v, 1);
        v += __shfl_xor_sync(0xFFFFFFFFu, v, 2);
        v += __shfl_xor_sync(0xFFFFFFFFu, v, 4);
        if ((t & 7) == 0) g_rownorm[block_m + p * 16 + ar] = v;
    }

    // ---- epilogue: write S ----
    #pragma unroll
    for (int mi = 0; mi < 2; mi++) {
        #pragma unroll
        for (int ni = 0; ni < 8; ni++) {
            int row = block_m + warp_m + mi * 16 + lr;
            int col = warp_n + ni * 8 + lc;
            *(float2*)&g_S[(size_t)row * KG + col] =
                make_float2(acc[mi][ni][0], acc[mi][ni][1]);
            *(float2*)&g_S[(size_t)(row + 8) * KG + col] =
                make_float2(acc[mi][ni][2], acc[mi][ni][3]);
        }
    }
}

// ---------------- K3: per-row dist -> per-group sum of sqrt(dist) ----------------
__global__ void dist_kernel() {
    __shared__ float bins[KG];
    int t = threadIdx.x;
    if (t < KG) bins[t] = 0.0f;
    __syncthreads();
    int i = blockIdx.x * 256 + t;
    int b = i & (NB - 1);
    int g = g_gid[b];
    float s = g_S[(size_t)i * KG + g];
    float d2 = g_rownorm[i] - 2.0f * s + g_cnorm[g];
    float dist = sqrtf(fmaxf(d2, 0.0f));
    atomicAdd(&bins[g], sqrtf(dist));
    __syncthreads();
    if (t < KG) atomicAdd(&g_sqsum[t], bins[t]);
}

// ---------------- K4: density ----------------
__global__ void density_kernel() {
    int t = threadIdx.x;  // 128
    __shared__ float dens[KG];
    __shared__ float red[KG];
    __shared__ float sorted[KG];

    float cnt = g_counts[t];
    float d = (g_sqsum[t] / cnt) / logf(cnt + 10.0f);
    bool invalid = (cnt <= 1.0f);
    red[t] = invalid ? -3.4e38f : d;
    __syncthreads();
    for (int off = 64; off; off >>= 1) {
        if (t < off) red[t] = fmaxf(red[t], red[t + off]);
        __syncthreads();
    }
    float dmax = red[0];
    __syncthreads();
    if (invalid) d = dmax;
    dens[t] = d;
    __syncthreads();

    int rank = 0;
    float v = d;
    for (int j = 0; j < KG; j++) {
        float w = dens[j];
        rank += (int)((w < v) || ((w == v) && (j < t)));
    }
    sorted[rank] = v;
    __syncthreads();

    float qlo = sorted[12] + 0.7f * (sorted[13] - sorted[12]);
    float qhi = sorted[114] + 0.3f * (sorted[115] - sorted[114]);
    float dc = fminf(fmaxf(d, qlo), qhi);
    red[t] = dc;
    __syncthreads();
    for (int off = 64; off; off >>= 1) {
        if (t < off) red[t] += red[t + off];
        __syncthreads();
    }
    float mean = red[0] * (1.0f / 128.0f);
    float fin = 0.1f * dc / mean;
    g_invdens[t] = 1.0f / fin;
}

// ---------------- K5: masked log-softmax loss ----------------
__global__ __launch_bounds__(256) void loss_kernel(const int* __restrict__ subject,
                                                   const int* __restrict__ labels,
                                                   float* __restrict__ out) {
    int warp_in_block = threadIdx.x >> 5;
    int lane = threadIdx.x & 31;
    int i = blockIdx.x * 8 + warp_in_block;
    int b = i & (NB - 1);

    float4 sv = *(const float4*)&g_S[(size_t)i * KG + lane * 4];
    float4 idv = *(const float4*)&g_invdens[lane * 4];
    float s0 = sv.x * idv.x, s1 = sv.y * idv.y, s2 = sv.z * idv.z, s3 = sv.w * idv.w;

    float mx = fmaxf(fmaxf(s0, s1), fmaxf(s2, s3));
    #pragma unroll
    for (int off = 16; off; off >>= 1) mx = fmaxf(mx, __shfl_xor_sync(0xFFFFFFFFu, mx, off));

    int sub = subject[b];
    int lab = labels[b];

    float sim[4] = {s0, s1, s2, s3};
    float sumexp = 0.0f, possum = 0.0f;
    #pragma unroll
    for (int j = 0; j < 4; j++) {
        int g = lane * 4 + j;
        bool m = ((g & 7) == lab) && ((g >> 3) != sub);
        float p = m ? (sim[j] - mx) : 0.0f;
        sumexp += expf(p);
        possum += p;
    }
    #pragma unroll
    for (int off = 16; off; off >>= 1) {
        sumexp += __shfl_xor_sync(0xFFFFFFFFu, sumexp, off);
        possum += __shfl_xor_sync(0xFFFFFFFFu, possum, off);
    }

    __shared__ float wloss[8];
    if (lane == 0)
        wloss[warp_in_block] = logf(sumexp) - possum * (1.0f / 15.0f);
    __syncthreads();
    if (threadIdx.x == 0) {
        float s = 0.0f;
        #pragma unroll
        for (int w = 0; w < 8; w++) s += wloss[w];
        atomicAdd(out, s * (1.0f / (float)NROWS));
    }
}

// ---------------- launch ----------------
extern "C" void kernel_launch(void* const* d_in, const int* in_sizes, int n_in,
                              void* d_out, int out_size) {
    const float* X       = (const float*)d_in[0];
    const int*   subject = (const int*)d_in[1];
    const int*   labels  = (const int*)d_in[2];
    float* out = (float*)d_out;

    static bool attr_set = false;
    if (!attr_set) {
        cudaFuncSetAttribute(gemm_kernel,
                             cudaFuncAttributeMaxDynamicSharedMemorySize, DYN_SMEM);
        attr_set = true;
    }

    zero_kernel<<<1, 128>>>(out);
    hist_kernel<<<NB / 256, 256>>>(subject, labels);
    offsets_kernel<<<1, 128>>>();
    scatter_kernel<<<64, 256>>>();
    dim3 cgrid(ND / 256, KG);
    centroid_kernel<<<cgrid, 256>>>(X);
    gemm_kernel<<<NROWS / 64, 128, DYN_SMEM>>>(X);
    dist_kernel<<<NROWS / 256, 256>>>();
    density_kernel<<<1, 128>>>();
    loss_kernel<<<NROWS / 8, 256>>>(subject, labels, out);
}